// round 8
// baseline (speedup 1.0000x reference)
#include <cuda_runtime.h>
#include <math.h>

#define BATCH 128
#define SEQ 48
#define FEAT 60
#define NH 5
#define NV 6
#define TWO_PI 6.2831853071795864769f

struct C2 { float re, im; };
struct M2 { C2 m00, m01, m10, m11; };

__device__ __forceinline__ C2 cmul(C2 a, C2 b) {
    C2 r; r.re = a.re*b.re - a.im*b.im; r.im = a.re*b.im + a.im*b.re; return r;
}
__device__ __forceinline__ C2 cadd(C2 a, C2 b) { C2 r{a.re+b.re, a.im+b.im}; return r; }

__device__ __forceinline__ M2 fuse_zyx(float t1, float t2, float t3) {
    float c1,s1,c2,s2,c3,s3;
    sincosf(0.5f*t1, &s1, &c1);
    sincosf(0.5f*t2, &s2, &c2);
    sincosf(0.5f*t3, &s3, &c3);
    C2 a00{c1,0.f}, a01{0.f,-s1}, a10{0.f,-s1}, a11{c1,0.f};
    C2 m00{c2*a00.re - s2*a10.re, c2*a00.im - s2*a10.im};
    C2 m01{c2*a01.re - s2*a11.re, c2*a01.im - s2*a11.im};
    C2 m10{s2*a00.re + c2*a10.re, s2*a00.im + c2*a10.im};
    C2 m11{s2*a01.re + c2*a11.re, s2*a01.im + c2*a11.im};
    C2 r0{c3,-s3}, r1{c3,s3};
    M2 u;
    u.m00 = cmul(r0,m00); u.m01 = cmul(r0,m01);
    u.m10 = cmul(r1,m10); u.m11 = cmul(r1,m11);
    return u;
}
__device__ __forceinline__ M2 mmul(M2 p, M2 q) {
    M2 r;
    r.m00 = cadd(cmul(p.m00,q.m00), cmul(p.m01,q.m10));
    r.m01 = cadd(cmul(p.m00,q.m01), cmul(p.m01,q.m11));
    r.m10 = cadd(cmul(p.m10,q.m00), cmul(p.m11,q.m10));
    r.m11 = cadd(cmul(p.m10,q.m01), cmul(p.m11,q.m11));
    return r;
}

template<int M>
__device__ __forceinline__ void g1q(float* Sr, float* Si, M2 g) {
    #pragma unroll
    for (int i = 0; i < 32; ++i) {
        if ((i & M) == 0) {
            const int j = i | M;
            float ar = Sr[i], ai = Si[i], br = Sr[j], bi = Si[j];
            Sr[i] = g.m00.re*ar - g.m00.im*ai + g.m01.re*br - g.m01.im*bi;
            Si[i] = g.m00.re*ai + g.m00.im*ar + g.m01.re*bi + g.m01.im*br;
            Sr[j] = g.m10.re*ar - g.m10.im*ai + g.m11.re*br - g.m11.im*bi;
            Si[j] = g.m10.re*ai + g.m10.im*ar + g.m11.re*bi + g.m11.im*br;
        }
    }
}
template<int MC, int MT>
__device__ __forceinline__ void gcrx(float* Sr, float* Si, float c, float s) {
    #pragma unroll
    for (int i = 0; i < 32; ++i) {
        if ((i & MC) != 0 && (i & MT) == 0) {
            const int j = i | MT;
            float a0r = Sr[i], a0i = Si[i], a1r = Sr[j], a1i = Si[j];
            Sr[i] = c*a0r + s*a1i;
            Si[i] = c*a0i - s*a1r;
            Sr[j] = s*a0i + c*a1r;
            Si[j] = c*a1i - s*a0r;
        }
    }
}

__device__ __forceinline__ unsigned long long pack2(float lo, float hi) {
    unsigned long long r;
    asm("mov.b64 %0, {%1, %2};" : "=l"(r) : "r"(__float_as_uint(lo)), "r"(__float_as_uint(hi)));
    return r;
}
__device__ __forceinline__ void unpack2(unsigned long long v, float& lo, float& hi) {
    unsigned a, b;
    asm("mov.b64 {%0, %1}, %2;" : "=r"(a), "=r"(b) : "l"(v));
    lo = __uint_as_float(a); hi = __uint_as_float(b);
}
__device__ __forceinline__ void fma2(unsigned long long& acc, unsigned long long a, unsigned long long b) {
    asm("fma.rn.f32x2 %0, %1, %2, %0;" : "+l"(acc) : "l"(a), "l"(b));
}
__device__ __forceinline__ unsigned long long mul2(unsigned long long a, unsigned long long b) {
    unsigned long long r;
    asm("mul.rn.f32x2 %0, %1, %2;" : "=l"(r) : "l"(a), "l"(b));
    return r;
}

__global__ __launch_bounds__(128)
void qrnn_kernel(const float* __restrict__ x,
                 const float* __restrict__ hidden,
                 const float* __restrict__ params,
                 float* __restrict__ out)
{
    const int bb = blockIdx.x;          // pair index: batch elements 2*bb, 2*bb+1
    __shared__ float Tre[32][33];
    __shared__ float Tim[32][33];

    if (threadIdx.x < 32) {
        // ====== warp 0: TWO interleaved hidden recurrences (5-qubit sims) ======
        const int lane = threadIdx.x;
        const bool special = (__popc(lane) == 1) && (lane <= 16);
        const int q_of_lane = special ? (__clz(lane) - 27) : 0;   // lane16->q0 ... lane1->q4

        // ---- precompute U'' = CRX1 * G2 * CRX0 * G1 * Phase  (column per lane) ----
        unsigned long long PRr[16], PRi[16];
        {
            M2 h1[5], h2[5];
            #pragma unroll
            for (int q = 0; q < 5; q++) {
                h1[q] = fuse_zyx(params[3*q],    params[3*q+1],    params[3*q+2]);
                h2[q] = fuse_zyx(params[37+3*q], params[37+3*q+1], params[37+3*q+2]);
            }
            float cx[8], sx[8];
            #pragma unroll
            for (int k = 0; k < 8; k++) {
                int l = k >> 2, kk = k & 3;
                sincosf(0.5f*params[l*37 + 15 + kk], &sx[k], &cx[k]);
            }

            float Sr[32], Si[32];
            #pragma unroll
            for (int i = 0; i < 32; ++i) { Sr[i] = (i == lane) ? 1.f : 0.f; Si[i] = 0.f; }

            g1q<16>(Sr, Si, h1[0]);
            g1q< 8>(Sr, Si, h1[1]);
            g1q< 4>(Sr, Si, h1[2]);
            g1q< 2>(Sr, Si, h1[3]);
            g1q< 1>(Sr, Si, h1[4]);
            gcrx<16,8>(Sr, Si, cx[0], sx[0]);
            gcrx< 8,4>(Sr, Si, cx[1], sx[1]);
            gcrx< 4,2>(Sr, Si, cx[2], sx[2]);
            gcrx< 2,1>(Sr, Si, cx[3], sx[3]);
            g1q<16>(Sr, Si, h2[0]);
            g1q< 8>(Sr, Si, h2[1]);
            g1q< 4>(Sr, Si, h2[2]);
            g1q< 2>(Sr, Si, h2[3]);
            g1q< 1>(Sr, Si, h2[4]);
            gcrx<16,8>(Sr, Si, cx[4], sx[4]);
            gcrx< 8,4>(Sr, Si, cx[5], sx[5]);
            gcrx< 4,2>(Sr, Si, cx[6], sx[6]);
            gcrx< 2,1>(Sr, Si, cx[7], sx[7]);

            // fold embed phase (-i)^popc(column)
            {
                int k = __popc(lane) & 3;
                #pragma unroll
                for (int i = 0; i < 32; ++i) {
                    float r = Sr[i], im = Si[i];
                    if (k == 1)      { Sr[i] =  im; Si[i] = -r;  }
                    else if (k == 2) { Sr[i] = -r;  Si[i] = -im; }
                    else if (k == 3) { Sr[i] = -im; Si[i] =  r;  }
                }
            }

            #pragma unroll
            for (int i = 0; i < 32; ++i) { Tre[i][lane] = Sr[i]; Tim[i][lane] = Si[i]; }
            __syncwarp();
            #pragma unroll
            for (int j2 = 0; j2 < 16; ++j2) {
                PRr[j2] = pack2(Tre[lane][2*j2], Tre[lane][2*j2+1]);
                PRi[j2] = pack2(Tim[lane][2*j2], Tim[lane][2*j2+1]);
            }
        }

        float za = special ? hidden[(2*bb  )*NH + q_of_lane] : 0.f;
        float zb = special ? hidden[(2*bb+1)*NH + q_of_lane] : 0.f;

        #pragma unroll 1
        for (int t = 0; t < SEQ; ++t) {
            // ---- sincos both chains ----
            float cca, ssa, ccb, ssb;
            __sincosf(0.5f*za, &ssa, &cca);
            __sincosf(0.5f*zb, &ssb, &ccb);

            // ---- broadcast 5 (c,s) pairs per chain (independent shuffles) ----
            float a_c0 = __shfl_sync(0xffffffffu, cca, 16), a_s0 = __shfl_sync(0xffffffffu, ssa, 16);
            float b_c0 = __shfl_sync(0xffffffffu, ccb, 16), b_s0 = __shfl_sync(0xffffffffu, ssb, 16);
            float a_c1 = __shfl_sync(0xffffffffu, cca,  8), a_s1 = __shfl_sync(0xffffffffu, ssa,  8);
            float b_c1 = __shfl_sync(0xffffffffu, ccb,  8), b_s1 = __shfl_sync(0xffffffffu, ssb,  8);
            float a_c2 = __shfl_sync(0xffffffffu, cca,  4), a_s2 = __shfl_sync(0xffffffffu, ssa,  4);
            float b_c2 = __shfl_sync(0xffffffffu, ccb,  4), b_s2 = __shfl_sync(0xffffffffu, ssb,  4);
            float a_c3 = __shfl_sync(0xffffffffu, cca,  2), a_s3 = __shfl_sync(0xffffffffu, ssa,  2);
            float b_c3 = __shfl_sync(0xffffffffu, ccb,  2), b_s3 = __shfl_sync(0xffffffffu, ssb,  2);
            float a_c4 = __shfl_sync(0xffffffffu, cca,  1), a_s4 = __shfl_sync(0xffffffffu, ssa,  1);
            float b_c4 = __shfl_sync(0xffffffffu, ccb,  1), b_s4 = __shfl_sync(0xffffffffu, ssb,  1);

            // ---- local subset-product trees (qubits 0..3) ----
            float ta1[4], tb1[4];
            ta1[0]=a_c0*a_c1; ta1[1]=a_c0*a_s1; ta1[2]=a_s0*a_c1; ta1[3]=a_s0*a_s1;
            tb1[0]=b_c0*b_c1; tb1[1]=b_c0*b_s1; tb1[2]=b_s0*b_c1; tb1[3]=b_s0*b_s1;
            float ta2[8], tb2[8];
            #pragma unroll
            for (int k = 0; k < 4; ++k) {
                ta2[2*k]=ta1[k]*a_c2; ta2[2*k+1]=ta1[k]*a_s2;
                tb2[2*k]=tb1[k]*b_c2; tb2[2*k+1]=tb1[k]*b_s2;
            }
            float basea[16], baseb[16];
            #pragma unroll
            for (int k = 0; k < 8; ++k) {
                basea[2*k]=ta2[k]*a_c3; basea[2*k+1]=ta2[k]*a_s3;
                baseb[2*k]=tb2[k]*b_c3; baseb[2*k+1]=tb2[k]*b_s3;
            }
            const unsigned long long csa = pack2(a_c4, a_s4);
            const unsigned long long csb = pack2(b_c4, b_s4);

            // ---- two matvecs, interleaved (shared matrix registers) ----
            unsigned long long aR0=0ull, aR1=0ull, aI0=0ull, aI1=0ull;
            unsigned long long bR0=0ull, bR1=0ull, bI0=0ull, bI1=0ull;
            #pragma unroll
            for (int j2 = 0; j2 < 16; j2 += 2) {
                unsigned long long ma0 = mul2(pack2(basea[j2],   basea[j2]),   csa);
                unsigned long long mb0 = mul2(pack2(baseb[j2],   baseb[j2]),   csb);
                unsigned long long ma1 = mul2(pack2(basea[j2+1], basea[j2+1]), csa);
                unsigned long long mb1 = mul2(pack2(baseb[j2+1], baseb[j2+1]), csb);
                fma2(aR0, PRr[j2],   ma0);
                fma2(bR0, PRr[j2],   mb0);
                fma2(aI0, PRi[j2],   ma0);
                fma2(bI0, PRi[j2],   mb0);
                fma2(aR1, PRr[j2+1], ma1);
                fma2(bR1, PRr[j2+1], mb1);
                fma2(aI1, PRi[j2+1], ma1);
                fma2(bI1, PRi[j2+1], mb1);
            }
            float x0,x1,y0,y1,u0,u1,v0,v1;
            unpack2(aR0,x0,x1); unpack2(aR1,y0,y1);
            unpack2(aI0,u0,u1); unpack2(aI1,v0,v1);
            float nara = (x0+x1)+(y0+y1);
            float naia = (u0+u1)+(v0+v1);
            unpack2(bR0,x0,x1); unpack2(bR1,y0,y1);
            unpack2(bI0,u0,u1); unpack2(bI1,v0,v1);
            float narb = (x0+x1)+(y0+y1);
            float naib = (u0+u1)+(v0+v1);

            // ---- two Walsh-Hadamard signed butterflies (interleaved) ----
            float va = fmaf(nara, nara, naia*naia);
            float vb = fmaf(narb, narb, naib*naib);
            #pragma unroll
            for (int m2 = 16; m2 >= 1; m2 >>= 1) {
                float oa = __shfl_xor_sync(0xffffffffu, va, m2);
                float ob = __shfl_xor_sync(0xffffffffu, vb, m2);
                va = (lane & m2) ? (oa - va) : (va + oa);
                vb = (lane & m2) ? (ob - vb) : (vb + ob);
            }
            za = special ? va : 0.f;
            zb = special ? vb : 0.f;
        }
        if (special) {
            out[BATCH*SEQ*NV + (2*bb  )*NH + q_of_lane] = za;
            out[BATCH*SEQ*NV + (2*bb+1)*NH + q_of_lane] = zb;
        }

    } else {
        // ====== warps 1-3: closed-form outputs for both batch elements ======
        const int i = threadIdx.x - 32;       // 0..95
        const int b = 2*bb + (i / SEQ);
        const int t = i % SEQ;

        float Cc[6], Dd[6], Ee[6];
        #pragma unroll
        for (int q = 0; q < 6; q++) {
            M2 u0 = fuse_zyx(params[19+3*q],    params[20+3*q],    params[21+3*q]);
            M2 u1 = fuse_zyx(params[37+19+3*q], params[37+20+3*q], params[37+21+3*q]);
            M2 M = mmul(u1, u0);
            float h00 = (M.m00.re*M.m00.re + M.m00.im*M.m00.im)
                      - (M.m10.re*M.m10.re + M.m10.im*M.m10.im);
            float h11 = (M.m01.re*M.m01.re + M.m01.im*M.m01.im)
                      - (M.m11.re*M.m11.re + M.m11.im*M.m11.im);
            float imh01 = (M.m00.re*M.m01.im - M.m00.im*M.m01.re)
                        - (M.m10.re*M.m11.im - M.m10.im*M.m11.re);
            Cc[q] = 0.5f*(h00 + h11);
            Dd[q] = 0.5f*(h00 - h11);
            Ee[q] = imh01;
        }

        const int P = b * SEQ + t;
        const float4* x4 = (const float4*)(x + (size_t)P * FEAT);
        float vals[60];
        #pragma unroll
        for (int k = 0; k < 15; k++) {
            float4 v4 = x4[k];
            vals[4*k+0] = v4.x; vals[4*k+1] = v4.y;
            vals[4*k+2] = v4.z; vals[4*k+3] = v4.w;
        }
        float pooled[6];
        #pragma unroll
        for (int v = 0; v < 6; v++) {
            float s = 0.f;
            #pragma unroll
            for (int j = 0; j < 10; j++) s += vals[v*10 + j];
            pooled[v] = 0.1f * s;
        }
        float mn = pooled[0], mx = pooled[0];
        #pragma unroll
        for (int v = 1; v < 6; v++) {
            mn = fminf(mn, pooled[v]);
            mx = fmaxf(mx, pooled[v]);
        }
        float scale = TWO_PI / (mx - mn + 1e-8f);
        #pragma unroll
        for (int v = 0; v < 6; v++) {
            float a = scale * (pooled[v] - mn);
            float sa, ca;
            sincosf(a, &sa, &ca);
            out[(size_t)P*6 + v] = Cc[v] + Dd[v]*ca + Ee[v]*sa;
        }
    }
}

extern "C" void kernel_launch(void* const* d_in, const int* in_sizes, int n_in,
                              void* d_out, int out_size) {
    const float* x      = (const float*)d_in[0];
    const float* hidden = (const float*)d_in[1];
    const float* params = (const float*)d_in[2];
    float* out = (float*)d_out;
    qrnn_kernel<<<BATCH/2, 128>>>(x, hidden, params, out);
}

// round 9
// speedup vs baseline: 1.5144x; 1.5144x over previous
#include <cuda_runtime.h>
#include <math.h>

#define BATCH 128
#define SEQ 48
#define FEAT 60
#define NH 5
#define NV 6
#define TWO_PI 6.2831853071795864769f

struct C2 { float re, im; };
struct M2 { C2 m00, m01, m10, m11; };

__device__ __forceinline__ C2 cmul(C2 a, C2 b) {
    C2 r; r.re = a.re*b.re - a.im*b.im; r.im = a.re*b.im + a.im*b.re; return r;
}
__device__ __forceinline__ C2 cadd(C2 a, C2 b) { C2 r{a.re+b.re, a.im+b.im}; return r; }

// U = RZ(t3) * RY(t2) * RX(t1)
__device__ __forceinline__ M2 fuse_zyx(float t1, float t2, float t3) {
    float c1,s1,c2,s2,c3,s3;
    sincosf(0.5f*t1, &s1, &c1);
    sincosf(0.5f*t2, &s2, &c2);
    sincosf(0.5f*t3, &s3, &c3);
    C2 a00{c1,0.f}, a01{0.f,-s1}, a10{0.f,-s1}, a11{c1,0.f};
    C2 m00{c2*a00.re - s2*a10.re, c2*a00.im - s2*a10.im};
    C2 m01{c2*a01.re - s2*a11.re, c2*a01.im - s2*a11.im};
    C2 m10{s2*a00.re + c2*a10.re, s2*a00.im + c2*a10.im};
    C2 m11{s2*a01.re + c2*a11.re, s2*a01.im + c2*a11.im};
    C2 r0{c3,-s3}, r1{c3,s3};
    M2 u;
    u.m00 = cmul(r0,m00); u.m01 = cmul(r0,m01);
    u.m10 = cmul(r1,m10); u.m11 = cmul(r1,m11);
    return u;
}
__device__ __forceinline__ M2 mmul(M2 p, M2 q) {
    M2 r;
    r.m00 = cadd(cmul(p.m00,q.m00), cmul(p.m01,q.m10));
    r.m01 = cadd(cmul(p.m00,q.m01), cmul(p.m01,q.m11));
    r.m10 = cadd(cmul(p.m10,q.m00), cmul(p.m11,q.m10));
    r.m11 = cadd(cmul(p.m10,q.m01), cmul(p.m11,q.m11));
    return r;
}

// ---- cooperative SMEM gate stages: state S[amp][col], stride 33 ----
// thread handles 4 (g1q) or 2 (gcrx) pairs of its column.
template<int M>
__device__ __forceinline__ void g1q_s(float* Sre, float* Sim, int col, int w, const M2& g) {
    #pragma unroll
    for (int pp = 0; pp < 4; ++pp) {
        int p = 4*w + pp;
        int i = ((p & ~(M-1)) << 1) | (p & (M-1));
        int j = i | M;
        float ar = Sre[i*33+col], ai = Sim[i*33+col];
        float br = Sre[j*33+col], bi = Sim[j*33+col];
        Sre[i*33+col] = g.m00.re*ar - g.m00.im*ai + g.m01.re*br - g.m01.im*bi;
        Sim[i*33+col] = g.m00.re*ai + g.m00.im*ar + g.m01.re*bi + g.m01.im*br;
        Sre[j*33+col] = g.m10.re*ar - g.m10.im*ai + g.m11.re*br - g.m11.im*bi;
        Sim[j*33+col] = g.m10.re*ai + g.m10.im*ar + g.m11.re*bi + g.m11.im*br;
    }
}
template<int MC, int MT>
__device__ __forceinline__ void gcrx_s(float* Sre, float* Sim, int col, int w, float c, float s) {
    #pragma unroll
    for (int pp = 0; pp < 2; ++pp) {
        int p = 2*w + pp;
        int i = ((p & ~(MT-1)) << 2) | MC | (p & (MT-1));
        int j = i | MT;
        float a0r = Sre[i*33+col], a0i = Sim[i*33+col];
        float a1r = Sre[j*33+col], a1i = Sim[j*33+col];
        Sre[i*33+col] = c*a0r + s*a1i;
        Sim[i*33+col] = c*a0i - s*a1r;
        Sre[j*33+col] = s*a0i + c*a1r;
        Sim[j*33+col] = c*a1i - s*a0r;
    }
}

__device__ __forceinline__ unsigned long long pack2(float lo, float hi) {
    unsigned long long r;
    asm("mov.b64 %0, {%1, %2};" : "=l"(r) : "r"(__float_as_uint(lo)), "r"(__float_as_uint(hi)));
    return r;
}
__device__ __forceinline__ void unpack2(unsigned long long v, float& lo, float& hi) {
    unsigned a, b;
    asm("mov.b64 {%0, %1}, %2;" : "=r"(a), "=r"(b) : "l"(v));
    lo = __uint_as_float(a); hi = __uint_as_float(b);
}
__device__ __forceinline__ void fma2(unsigned long long& acc, unsigned long long a, unsigned long long b) {
    asm("fma.rn.f32x2 %0, %1, %2, %0;" : "+l"(acc) : "l"(a), "l"(b));
}
__device__ __forceinline__ unsigned long long mul2(unsigned long long a, unsigned long long b) {
    unsigned long long r;
    asm("mul.rn.f32x2 %0, %1, %2;" : "=l"(r) : "l"(a), "l"(b));
    return r;
}

__global__ __launch_bounds__(128)
void qrnn_kernel(const float* __restrict__ x,
                 const float* __restrict__ hidden,
                 const float* __restrict__ params,
                 float* __restrict__ out)
{
    const int b   = blockIdx.x;
    const int tid = threadIdx.x;
    const int col = tid & 31;
    const int w   = tid >> 5;

    __shared__ float Sre[32*33];
    __shared__ float Sim[32*33];

    // ======== cooperative precompute of U'' = CRX1*G2*CRX0*G1 (all 128 threads) ========
    {
        M2 h1[5], h2[5];
        #pragma unroll
        for (int q = 0; q < 5; q++) {
            h1[q] = fuse_zyx(params[3*q],    params[3*q+1],    params[3*q+2]);
            h2[q] = fuse_zyx(params[37+3*q], params[37+3*q+1], params[37+3*q+2]);
        }
        float cx[8], sx[8];
        #pragma unroll
        for (int k = 0; k < 8; k++) {
            int l = k >> 2, kk = k & 3;
            sincosf(0.5f*params[l*37 + 15 + kk], &sx[k], &cx[k]);
        }

        // identity columns
        #pragma unroll
        for (int r = 0; r < 8; ++r) {
            int i = 8*w + r;
            Sre[i*33 + col] = (i == col) ? 1.f : 0.f;
            Sim[i*33 + col] = 0.f;
        }
        __syncthreads();

        // layer-0 1q gates
        g1q_s<16>(Sre, Sim, col, w, h1[0]); __syncthreads();
        g1q_s< 8>(Sre, Sim, col, w, h1[1]); __syncthreads();
        g1q_s< 4>(Sre, Sim, col, w, h1[2]); __syncthreads();
        g1q_s< 2>(Sre, Sim, col, w, h1[3]); __syncthreads();
        g1q_s< 1>(Sre, Sim, col, w, h1[4]); __syncthreads();
        // layer-0 CRX chain
        gcrx_s<16,8>(Sre, Sim, col, w, cx[0], sx[0]); __syncthreads();
        gcrx_s< 8,4>(Sre, Sim, col, w, cx[1], sx[1]); __syncthreads();
        gcrx_s< 4,2>(Sre, Sim, col, w, cx[2], sx[2]); __syncthreads();
        gcrx_s< 2,1>(Sre, Sim, col, w, cx[3], sx[3]); __syncthreads();
        // layer-1 1q gates
        g1q_s<16>(Sre, Sim, col, w, h2[0]); __syncthreads();
        g1q_s< 8>(Sre, Sim, col, w, h2[1]); __syncthreads();
        g1q_s< 4>(Sre, Sim, col, w, h2[2]); __syncthreads();
        g1q_s< 2>(Sre, Sim, col, w, h2[3]); __syncthreads();
        g1q_s< 1>(Sre, Sim, col, w, h2[4]); __syncthreads();
        // layer-1 CRX chain
        gcrx_s<16,8>(Sre, Sim, col, w, cx[4], sx[4]); __syncthreads();
        gcrx_s< 8,4>(Sre, Sim, col, w, cx[5], sx[5]); __syncthreads();
        gcrx_s< 4,2>(Sre, Sim, col, w, cx[6], sx[6]); __syncthreads();
        gcrx_s< 2,1>(Sre, Sim, col, w, cx[7], sx[7]); __syncthreads();
    }

    if (tid < 32) {
        // ================= warp 0: hidden recurrence loop =================
        const int lane = tid;
        const bool special = (__popc(lane) == 1) && (lane <= 16);
        const int q_of_lane = special ? (__clz(lane) - 27) : 0;   // lane16->q0 ... lane1->q4

        // layer-0 hidden gate for this lane's qubit (for the embed 2-vector)
        M2 h1 = fuse_zyx(params[3*q_of_lane], params[3*q_of_lane+1], params[3*q_of_lane+2]);
        // NOTE: h1 was folded into U''; the per-step input is the raw product state,
        // so the loop only needs cos/sin of z (h1 above is NOT applied again).
        (void)h1;

        // read ROW lane of U'', fold embed phase (-i)^popc(col), pack column pairs
        unsigned long long PRr[16], PRi[16];
        #pragma unroll
        for (int j2 = 0; j2 < 16; ++j2) {
            float re0 = Sre[lane*33 + 2*j2],   im0 = Sim[lane*33 + 2*j2];
            float re1 = Sre[lane*33 + 2*j2+1], im1 = Sim[lane*33 + 2*j2+1];
            int k0 = __popc(2*j2) & 3, k1 = __popc(2*j2+1) & 3;
            float a0, b0, a1, b1;
            if (k0 == 0)      { a0 =  re0; b0 =  im0; }
            else if (k0 == 1) { a0 =  im0; b0 = -re0; }
            else if (k0 == 2) { a0 = -re0; b0 = -im0; }
            else              { a0 = -im0; b0 =  re0; }
            if (k1 == 0)      { a1 =  re1; b1 =  im1; }
            else if (k1 == 1) { a1 =  im1; b1 = -re1; }
            else if (k1 == 2) { a1 = -re1; b1 = -im1; }
            else              { a1 = -im1; b1 =  re1; }
            PRr[j2] = pack2(a0, a1);
            PRi[j2] = pack2(b0, b1);
        }

        float z = special ? hidden[b*NH + q_of_lane] : 0.f;

        #pragma unroll 1
        for (int t = 0; t < SEQ; ++t) {
            // ---- sincos on special lanes; broadcast 5 (c,s) pairs ----
            float cc, ss;
            __sincosf(0.5f*z, &ss, &cc);
            float c0 = __shfl_sync(0xffffffffu, cc, 16), s0 = __shfl_sync(0xffffffffu, ss, 16);
            float c1 = __shfl_sync(0xffffffffu, cc,  8), s1 = __shfl_sync(0xffffffffu, ss,  8);
            float c2 = __shfl_sync(0xffffffffu, cc,  4), s2 = __shfl_sync(0xffffffffu, ss,  4);
            float c3 = __shfl_sync(0xffffffffu, cc,  2), s3 = __shfl_sync(0xffffffffu, ss,  2);
            float c4 = __shfl_sync(0xffffffffu, cc,  1), s4 = __shfl_sync(0xffffffffu, ss,  1);

            // ---- group products over qubits 0..2 (8 groups), pair consts over q3,q4 ----
            float g01_0 = c0*c1, g01_1 = c0*s1, g01_2 = s0*c1, g01_3 = s0*s1;
            float g0 = g01_0*c2, g1 = g01_0*s2, g2 = g01_1*c2, g3 = g01_1*s2;
            float g4 = g01_2*c2, g5 = g01_2*s2, g6 = g01_3*c2, g7 = g01_3*s2;
            const unsigned long long pa = pack2(c3*c4, c3*s4);
            const unsigned long long pb = pack2(s3*c4, s3*s4);

            // ---- matvec amp' = U'' * m, m generated 4 columns at a time ----
            unsigned long long aR0=0ull, aR1=0ull, aI0=0ull, aI1=0ull;
            #define STEP(k, g)                                             \
            {                                                              \
                unsigned long long gg = pack2(g, g);                       \
                unsigned long long m0 = mul2(gg, pa);                      \
                unsigned long long m1 = mul2(gg, pb);                      \
                fma2(aR0, PRr[2*(k)],   m0);                               \
                fma2(aI0, PRi[2*(k)],   m0);                               \
                fma2(aR1, PRr[2*(k)+1], m1);                               \
                fma2(aI1, PRi[2*(k)+1], m1);                               \
            }
            STEP(0, g0) STEP(1, g1) STEP(2, g2) STEP(3, g3)
            STEP(4, g4) STEP(5, g5) STEP(6, g6) STEP(7, g7)
            #undef STEP

            float x0,x1,y0,y1,u0,u1,v0,v1;
            unpack2(aR0,x0,x1); unpack2(aR1,y0,y1);
            unpack2(aI0,u0,u1); unpack2(aI1,v0,v1);
            float nar = (x0+x1)+(y0+y1);
            float nai = (u0+u1)+(v0+v1);

            // ---- measure: Walsh-Hadamard signed butterfly; lane 1<<(4-q) keeps z_q ----
            float v = fmaf(nar, nar, nai*nai);
            #pragma unroll
            for (int m2 = 16; m2 >= 1; m2 >>= 1) {
                float o = __shfl_xor_sync(0xffffffffu, v, m2);
                v = (lane & m2) ? (o - v) : (v + o);
            }
            z = special ? v : 0.f;
        }
        if (special) out[BATCH*SEQ*NV + b*NH + q_of_lane] = z;

    } else {
        // ============ warps 1-3: closed-form outputs for this batch ============
        const int t = tid - 32;
        if (t >= SEQ) return;

        float Cc[6], Dd[6], Ee[6];
        #pragma unroll
        for (int q = 0; q < 6; q++) {
            M2 u0 = fuse_zyx(params[19+3*q],    params[20+3*q],    params[21+3*q]);
            M2 u1 = fuse_zyx(params[37+19+3*q], params[37+20+3*q], params[37+21+3*q]);
            M2 M = mmul(u1, u0);
            float h00 = (M.m00.re*M.m00.re + M.m00.im*M.m00.im)
                      - (M.m10.re*M.m10.re + M.m10.im*M.m10.im);
            float h11 = (M.m01.re*M.m01.re + M.m01.im*M.m01.im)
                      - (M.m11.re*M.m11.re + M.m11.im*M.m11.im);
            float imh01 = (M.m00.re*M.m01.im - M.m00.im*M.m01.re)
                        - (M.m10.re*M.m11.im - M.m10.im*M.m11.re);
            Cc[q] = 0.5f*(h00 + h11);
            Dd[q] = 0.5f*(h00 - h11);
            Ee[q] = imh01;
        }

        const int P = b * SEQ + t;
        const float4* x4 = (const float4*)(x + (size_t)P * FEAT);
        float vals[60];
        #pragma unroll
        for (int k = 0; k < 15; k++) {
            float4 v4 = x4[k];
            vals[4*k+0] = v4.x; vals[4*k+1] = v4.y;
            vals[4*k+2] = v4.z; vals[4*k+3] = v4.w;
        }
        float pooled[6];
        #pragma unroll
        for (int v = 0; v < 6; v++) {
            float s = 0.f;
            #pragma unroll
            for (int j = 0; j < 10; j++) s += vals[v*10 + j];
            pooled[v] = 0.1f * s;
        }
        float mn = pooled[0], mx = pooled[0];
        #pragma unroll
        for (int v = 1; v < 6; v++) {
            mn = fminf(mn, pooled[v]);
            mx = fmaxf(mx, pooled[v]);
        }
        float scale = TWO_PI / (mx - mn + 1e-8f);
        #pragma unroll
        for (int v = 0; v < 6; v++) {
            float a = scale * (pooled[v] - mn);
            float sa, ca;
            sincosf(a, &sa, &ca);
            out[(size_t)P*6 + v] = Cc[v] + Dd[v]*ca + Ee[v]*sa;
        }
    }
}

extern "C" void kernel_launch(void* const* d_in, const int* in_sizes, int n_in,
                              void* d_out, int out_size) {
    const float* x      = (const float*)d_in[0];
    const float* hidden = (const float*)d_in[1];
    const float* params = (const float*)d_in[2];
    float* out = (float*)d_out;
    qrnn_kernel<<<BATCH, 128>>>(x, hidden, params, out);
}